// round 6
// baseline (speedup 1.0000x reference)
#include <cuda_runtime.h>
#include <cuda_fp16.h>
#include <math.h>

#define NN  50000   // nodes
#define EE  800000  // edges
#define LL  100000  // label edges
#define HH  8       // heads
#define FD  32      // hidden
#define HC  256     // H*C

// ---------------- scratch (device globals) --------------------------------------
__device__ float  g_x[NN * FD];           // node features entering a GAT layer (fp32)
__device__ __half g_xh[NN * FD];          // same, fp16 (gathered in agg)
__device__ float  g_alsrc[NN * HH];
__device__ float  g_aldst[NN * HH];
__device__ float  g_alpha[(size_t)EE * HH]; // alpha (CSR order) -> ex after softmax
__device__ float  g_rinv[NN * HH];          // 1/denom per (node, head)
__device__ float  g_agg[(size_t)NN * HC];   // h-space output of agg (z @ W blockdiag)
__device__ float  g_x5[NN * HH];
__device__ float  g_Psrc[2][FD * HH];
__device__ float  g_Pdst[2][FD * HH];
__device__ float  g_M[2][HH * HH];
// CSR by destination
__device__ int g_deg[NN];
__device__ int g_rowptr[NN + 1];
__device__ int g_cursor[NN];
__device__ int g_srcp[EE];   // src node per CSR slot
__device__ int g_slot[EE];   // CSR slot per original edge

// ---------------- precompute both layers: P_src/P_dst [32,8], M [8,8] ----------
__global__ void k_precompute(const float* __restrict__ W1,  const float* __restrict__ as1,
                             const float* __restrict__ ad1, const float* __restrict__ We1,
                             const float* __restrict__ ae1,
                             const float* __restrict__ W2,  const float* __restrict__ as2,
                             const float* __restrict__ ad2, const float* __restrict__ We2,
                             const float* __restrict__ ae2)
{
    int layer = blockIdx.x;
    const float* W   = layer ? W2  : W1;
    const float* a_s = layer ? as2 : as1;
    const float* a_d = layer ? ad2 : ad1;
    const float* We  = layer ? We2 : We1;
    const float* a_e = layer ? ae2 : ae1;

    int t = threadIdx.x;           // 256 threads
    int f = t >> 3, h = t & 7;
    float ss = 0.f, sd = 0.f;
    #pragma unroll 8
    for (int c = 0; c < FD; c++) {
        float w = W[f * HC + h * FD + c];
        ss = fmaf(w, a_s[h * FD + c], ss);
        sd = fmaf(w, a_d[h * FD + c], sd);
    }
    g_Psrc[layer][f * HH + h] = ss;
    g_Pdst[layer][f * HH + h] = sd;
    if (t < 64) {
        int k = t >> 3;
        float sm = 0.f;
        #pragma unroll 8
        for (int c = 0; c < FD; c++)
            sm = fmaf(We[k * HC + h * FD + c], a_e[h * FD + c], sm);
        g_M[layer][k * HH + h] = sm;
    }
}

// ---------------- CSR build -----------------------------------------------------
__global__ void k_zero_deg(void) {
    int i = blockIdx.x * 256 + threadIdx.x;
    if (i < NN) g_deg[i] = 0;
}
__global__ void k_hist(const int* __restrict__ dst) {
    int e = blockIdx.x * 256 + threadIdx.x;
    if (e < EE) atomicAdd(&g_deg[dst[e]], 1);
}
__global__ void __launch_bounds__(1024)
k_scan(void) {
    const int CH = (NN + 1023) / 1024;   // 49
    __shared__ int sums[1024];
    int t = threadIdx.x;
    int base = t * CH;
    int s = 0;
    for (int i = 0; i < CH; i++) {
        int idx = base + i;
        if (idx < NN) s += g_deg[idx];
    }
    sums[t] = s;
    __syncthreads();
    for (int off = 1; off < 1024; off <<= 1) {
        int v = (t >= off) ? sums[t - off] : 0;
        __syncthreads();
        sums[t] += v;
        __syncthreads();
    }
    int run = (t > 0) ? sums[t - 1] : 0;
    for (int i = 0; i < CH; i++) {
        int idx = base + i;
        if (idx < NN) {
            g_rowptr[idx] = run;
            g_cursor[idx] = run;
            run += g_deg[idx];
        }
    }
    if (t == 1023) g_rowptr[NN] = run;
}
__global__ void k_scatter(const int* __restrict__ src, const int* __restrict__ dst) {
    int e = blockIdx.x * 256 + threadIdx.x;
    if (e >= EE) return;
    int d = dst[e];
    int slot = atomicAdd(&g_cursor[d], 1);
    g_srcp[slot] = src[e];   // scattered store
    g_slot[e]    = slot;     // coalesced store
}

// ---------------- node prep: x fp16 + al_src/al_dst (NO GEMM anymore) ----------
__global__ void __launch_bounds__(256)
k_node(const float* __restrict__ xin, const int* __restrict__ ids, int layer)
{
    __shared__ float xs[32 * 36];
    __shared__ float Ps[FD * HH], Pd[FD * HH];
    int t  = threadIdx.x;
    int n0 = blockIdx.x * 32;

    Ps[t] = g_Psrc[layer][t];
    Pd[t] = g_Pdst[layer][t];
    const float* xp = xin ? xin : g_x;
    for (int i = t; i < 32 * FD; i += 256) {
        int n = i >> 5, k = i & 31;
        int node = n0 + n;
        float v = 0.f;
        if (node < NN) {
            int r = ids ? ids[node] : node;
            v = xp[(size_t)r * FD + k];
        }
        xs[n * 36 + k] = v;
    }
    __syncthreads();

    // write fp16 x
    for (int i = t; i < 32 * FD; i += 256) {
        int n = i >> 5, k = i & 31;
        if (n0 + n < NN)
            g_xh[(size_t)(n0 + n) * FD + k] = __float2half(xs[n * 36 + k]);
    }

    // attention matvecs
    int n = t >> 3, h = t & 7;
    if (n0 + n < NN) {
        float ss = 0.f, sd = 0.f;
        #pragma unroll
        for (int k = 0; k < FD; k++) {
            float xv = xs[n * 36 + k];
            ss = fmaf(xv, Ps[k * HH + h], ss);
            sd = fmaf(xv, Pd[k * HH + h], sd);
        }
        g_alsrc[(n0 + n) * HH + h] = ss;
        g_aldst[(n0 + n) * HH + h] = sd;
    }
}

// ---------------- edge: alpha = lrelu(al_src[s]+al_dst[d]+ea@M) -> CSR slot -----
__global__ void __launch_bounds__(256)
k_edge_alpha(const int* __restrict__ src, const int* __restrict__ dst,
             const float* __restrict__ ea, int layer)
{
    __shared__ float Ms[64];
    if (threadIdx.x < 64) Ms[threadIdx.x] = g_M[layer][threadIdx.x];
    __syncthreads();
    int e = blockIdx.x * 256 + threadIdx.x;
    if (e >= EE) return;
    int s = src[e], d = dst[e];
    int p = g_slot[e];

    float4 e0 = *(const float4*)(ea + (size_t)e * 8);
    float4 e1 = *(const float4*)(ea + (size_t)e * 8 + 4);
    float4 s0 = *(const float4*)(g_alsrc + (size_t)s * 8);
    float4 s1 = *(const float4*)(g_alsrc + (size_t)s * 8 + 4);
    float4 d0 = *(const float4*)(g_aldst + (size_t)d * 8);
    float4 d1 = *(const float4*)(g_aldst + (size_t)d * 8 + 4);

    float al[8] = { s0.x + d0.x, s0.y + d0.y, s0.z + d0.z, s0.w + d0.w,
                    s1.x + d1.x, s1.y + d1.y, s1.z + d1.z, s1.w + d1.w };
    float ev[8] = { e0.x, e0.y, e0.z, e0.w, e1.x, e1.y, e1.z, e1.w };
    #pragma unroll
    for (int k = 0; k < 8; k++)
        #pragma unroll
        for (int h = 0; h < 8; h++)
            al[h] = fmaf(ev[k], Ms[k * 8 + h], al[h]);
    #pragma unroll
    for (int h = 0; h < 8; h++) al[h] = al[h] > 0.f ? al[h] : 0.2f * al[h];

    *(float4*)(g_alpha + (size_t)p * 8)     = make_float4(al[0], al[1], al[2], al[3]);
    *(float4*)(g_alpha + (size_t)p * 8 + 4) = make_float4(al[4], al[5], al[6], al[7]);
}

// ---------------- per-node softmax: max, then exp+sum (write ex, store rinv) ----
__global__ void __launch_bounds__(256)
k_softmax(void)
{
    int n    = (blockIdx.x * 256 + threadIdx.x) >> 5;
    int lane = threadIdx.x & 31;
    if (n >= NN) return;
    int r0 = g_rowptr[n], r1 = g_rowptr[n + 1];
    int deg = r1 - r0;
    if (deg == 0) return;

    int h  = lane & 7;
    int eg = lane >> 3;

    float m = -INFINITY;
    for (int i = eg; i < deg; i += 4)
        m = fmaxf(m, g_alpha[(size_t)(r0 + i) * 8 + h]);
    m = fmaxf(m, __shfl_xor_sync(0xffffffffu, m, 8));
    m = fmaxf(m, __shfl_xor_sync(0xffffffffu, m, 16));

    float s = 0.f;
    for (int i = eg; i < deg; i += 4) {
        size_t idx = (size_t)(r0 + i) * 8 + h;
        float ex = expf(g_alpha[idx] - m);
        g_alpha[idx] = ex;
        s += ex;
    }
    s += __shfl_xor_sync(0xffffffffu, s, 8);
    s += __shfl_xor_sync(0xffffffffu, s, 16);
    if (lane < 8) g_rinv[(size_t)n * 8 + lane] = 1.f / (s + 1e-16f);
}

// ---------------- agg in x-space + fused block-diag GEMM (warp per node) --------
// z[n,h,k] = rinv[h] * sum_e ex_e * x[s_e,k]   (64B gather per edge!)
// g_agg[n, h*32+c] = sum_k z[n,h,k] * W[k, h*32+c]
__global__ void __launch_bounds__(256)
k_agg_csr(const float* __restrict__ W)
{
    __shared__ float Ws[FD * HC];   // 32KB: W [32, 256] row-major
    for (int i = threadIdx.x; i < FD * HC; i += 256) Ws[i] = W[i];
    __syncthreads();

    int n    = (blockIdx.x * 256 + threadIdx.x) >> 5;
    int lane = threadIdx.x & 31;
    if (n >= NN) return;
    int r0 = g_rowptr[n], r1 = g_rowptr[n + 1];

    int head = lane >> 2;      // z head owned by this lane
    int q    = lane & 3;       // k-quarter: k in [q*8, q*8+8)
    float acc[8];
    #pragma unroll
    for (int i = 0; i < 8; i++) acc[i] = 0.f;

    for (int p = r0; p < r1; p += 8) {
        int cnt = r1 - p;
        // 8 edges' ex weights = 64 consecutive floats; two coalesced lane loads
        size_t wbase = (size_t)p * 8;
        size_t wlim  = (size_t)r1 * 8 - 1;
        size_t ia = wbase + lane;      if (ia > wlim) ia = wlim;
        size_t ib = wbase + 32 + lane; if (ib > wlim) ib = wlim;
        float w_a = g_alpha[ia];
        float w_b = g_alpha[ib];

        int sj[8];
        #pragma unroll
        for (int j = 0; j < 8; j++) {
            int pp = p + j; if (pp >= r1) pp = r1 - 1;
            sj[j] = g_srcp[pp];
        }
        // gather 16B of x per lane per edge (8 outstanding)
        uint4 v[8];
        #pragma unroll
        for (int j = 0; j < 8; j++)
            v[j] = *(const uint4*)(g_xh + (size_t)sj[j] * FD + q * 8);
        #pragma unroll
        for (int j = 0; j < 8; j++) {
            float w = __shfl_sync(0xffffffffu, (j < 4) ? w_a : w_b,
                                  (j & 3) * 8 + head);
            if (j >= cnt) w = 0.f;
            float2 f0 = __half22float2(*(const __half2*)&v[j].x);
            float2 f1 = __half22float2(*(const __half2*)&v[j].y);
            float2 f2 = __half22float2(*(const __half2*)&v[j].z);
            float2 f3 = __half22float2(*(const __half2*)&v[j].w);
            acc[0] = fmaf(f0.x, w, acc[0]); acc[1] = fmaf(f0.y, w, acc[1]);
            acc[2] = fmaf(f1.x, w, acc[2]); acc[3] = fmaf(f1.y, w, acc[3]);
            acc[4] = fmaf(f2.x, w, acc[4]); acc[5] = fmaf(f2.y, w, acc[5]);
            acc[6] = fmaf(f3.x, w, acc[6]); acc[7] = fmaf(f3.y, w, acc[7]);
        }
    }
    // normalize z by softmax denom
    float rinv = (r0 < r1) ? g_rinv[(size_t)n * 8 + head] : 0.f;
    #pragma unroll
    for (int i = 0; i < 8; i++) acc[i] *= rinv;

    // block-diag GEMM: hout[c] = sum_k z[head,k] * W[k, lane*8 + c]
    // z[head, srcq*8 + j] lives in lane (head*4 + srcq), register acc[j]
    float hout[8];
    #pragma unroll
    for (int i = 0; i < 8; i++) hout[i] = 0.f;
    #pragma unroll
    for (int srcq = 0; srcq < 4; srcq++) {
        #pragma unroll
        for (int j = 0; j < 8; j++) {
            float zk = __shfl_sync(0xffffffffu, acc[j], (head << 2) + srcq);
            int k = srcq * 8 + j;
            float4 w0 = *(const float4*)&Ws[k * HC + lane * 8];
            float4 w1 = *(const float4*)&Ws[k * HC + lane * 8 + 4];
            hout[0] = fmaf(zk, w0.x, hout[0]); hout[1] = fmaf(zk, w0.y, hout[1]);
            hout[2] = fmaf(zk, w0.z, hout[2]); hout[3] = fmaf(zk, w0.w, hout[3]);
            hout[4] = fmaf(zk, w1.x, hout[4]); hout[5] = fmaf(zk, w1.y, hout[5]);
            hout[6] = fmaf(zk, w1.z, hout[6]); hout[7] = fmaf(zk, w1.w, hout[7]);
        }
    }
    float* po = g_agg + (size_t)n * HC + lane * 8;
    *(float4*)(po)     = make_float4(hout[0], hout[1], hout[2], hout[3]);
    *(float4*)(po + 4) = make_float4(hout[4], hout[5], hout[6], hout[7]);
}

// ---------------- epilogue: y = relu(agg + b) @ LW + lb ------------------------
template <int NJ>
__global__ void __launch_bounds__(256)
k_epi(const float* __restrict__ bias, const float* __restrict__ LW,
      const float* __restrict__ lb)
{
    constexpr int NODES = 256 / NJ;
    __shared__ float rows[NODES * 260];
    __shared__ float LWt[NJ * 260];       // transposed, padded stride
    int t  = threadIdx.x;
    int n0 = blockIdx.x * NODES;

    for (int i = t; i < HC * NJ; i += 256) {
        int c = i / NJ, j = i % NJ;
        LWt[j * 260 + c] = LW[i];
    }
    for (int i = t; i < NODES * HC; i += 256) {
        int n = i >> 8, c = i & 255;
        float v = 0.f;
        if (n0 + n < NN) v = g_agg[(size_t)(n0 + n) * HC + c] + bias[c];
        rows[n * 260 + c] = fmaxf(v, 0.f);
    }
    __syncthreads();

    int n = t / NJ, j = t % NJ;
    if (n0 + n < NN) {
        float acc = lb[j];
        #pragma unroll
        for (int c4 = 0; c4 < 64; c4++) {
            float4 r  = *(const float4*)&rows[n * 260 + c4 * 4];
            float4 wv = *(const float4*)&LWt[j * 260 + c4 * 4];
            acc = fmaf(r.x, wv.x, acc);
            acc = fmaf(r.y, wv.y, acc);
            acc = fmaf(r.z, wv.z, acc);
            acc = fmaf(r.w, wv.w, acc);
        }
        if (NJ == 32) g_x [(size_t)(n0 + n) * 32 + j] = acc;
        else          g_x5[(size_t)(n0 + n) * 8  + j] = acc;
    }
}

// ---------------- classifier over label edges ---------------------------------
__global__ void __launch_bounds__(256)
k_clf(const int* __restrict__ eli, const float* __restrict__ ela,
      const float* __restrict__ cW, const float* __restrict__ cb,
      float* __restrict__ outp)
{
    __shared__ float Ws[128], Bs[8];
    if (threadIdx.x < 128) Ws[threadIdx.x] = cW[threadIdx.x];
    if (threadIdx.x < 8)   Bs[threadIdx.x] = cb[threadIdx.x];
    __syncthreads();
    int l = blockIdx.x * 256 + threadIdx.x;
    if (l >= LL) return;
    int u = eli[l], m = eli[LL + l];

    float4 u0 = *(const float4*)(g_x5 + (size_t)u * 8);
    float4 u1 = *(const float4*)(g_x5 + (size_t)u * 8 + 4);
    float4 m0 = *(const float4*)(g_x5 + (size_t)m * 8);
    float4 m1 = *(const float4*)(g_x5 + (size_t)m * 8 + 4);
    float4 a0 = *(const float4*)(ela + (size_t)l * 8);
    float4 a1 = *(const float4*)(ela + (size_t)l * 8 + 4);
    float xu[8] = { u0.x, u0.y, u0.z, u0.w, u1.x, u1.y, u1.z, u1.w };
    float xm[8] = { m0.x, m0.y, m0.z, m0.w, m1.x, m1.y, m1.z, m1.w };
    float ev[8] = { a0.x, a0.y, a0.z, a0.w, a1.x, a1.y, a1.z, a1.w };

    float dot = 0.f;
    #pragma unroll
    for (int j = 0; j < 8; j++) {
        float fu = Bs[j];
        #pragma unroll
        for (int k = 0; k < 8; k++) fu = fmaf(xu[k], Ws[k * 8 + j], fu);
        #pragma unroll
        for (int k = 0; k < 8; k++) fu = fmaf(ev[k], Ws[(8 + k) * 8 + j], fu);
        dot = fmaf(fu, xm[j], dot);
    }
    outp[l] = 1.f / (1.f + expf(-dot));
}

// ---------------- launch -------------------------------------------------------
extern "C" void kernel_launch(void* const* d_in, const int* in_sizes, int n_in,
                              void* d_out, int out_size)
{
    const int*   node_ids = (const int*)d_in[0];
    const int*   ei   = (const int*)d_in[1];
    const int*   eli  = (const int*)d_in[2];
    const float* ea   = (const float*)d_in[4];
    const float* ela  = (const float*)d_in[5];
    const float* emb  = (const float*)d_in[6];
    const float* W1   = (const float*)d_in[7];
    const float* as1  = (const float*)d_in[8];
    const float* ad1  = (const float*)d_in[9];
    const float* We1  = (const float*)d_in[10];
    const float* ae1  = (const float*)d_in[11];
    const float* b1   = (const float*)d_in[12];
    const float* l1W  = (const float*)d_in[13];
    const float* l1b  = (const float*)d_in[14];
    const float* W2   = (const float*)d_in[15];
    const float* as2  = (const float*)d_in[16];
    const float* ad2  = (const float*)d_in[17];
    const float* We2  = (const float*)d_in[18];
    const float* ae2  = (const float*)d_in[19];
    const float* b2   = (const float*)d_in[20];
    const float* l5W  = (const float*)d_in[21];
    const float* l5b  = (const float*)d_in[22];
    const float* cW   = (const float*)d_in[23];
    const float* cb   = (const float*)d_in[24];
    float* out = (float*)d_out;

    const int* srce = ei;
    const int* dste = ei + EE;

    const int GB_NODE = (NN + 31) / 32;            // 1563
    const int GB_EDGE = (EE + 255) / 256;          // 3125
    const int GB_WARP = (NN * 32 + 255) / 256;     // 6250 (warp per node)
    const int GB_N256 = (NN + 255) / 256;          // 196

    // CSR build (shared by both layers)
    k_zero_deg<<<GB_N256, 256>>>();
    k_hist<<<GB_EDGE, 256>>>(dste);
    k_scan<<<1, 1024>>>();
    k_scatter<<<GB_EDGE, 256>>>(srce, dste);

    k_precompute<<<2, 256>>>(W1, as1, ad1, We1, ae1, W2, as2, ad2, We2, ae2);

    // ---- layer 1 ----
    k_node<<<GB_NODE, 256>>>(emb, node_ids, 0);
    k_edge_alpha<<<GB_EDGE, 256>>>(srce, dste, ea, 0);
    k_softmax<<<GB_WARP, 256>>>();
    k_agg_csr<<<GB_WARP, 256>>>(W1);
    k_epi<32><<<(NN + 7) / 8, 256>>>(b1, l1W, l1b);

    // ---- layer 2 ----
    k_node<<<GB_NODE, 256>>>(nullptr, nullptr, 1);
    k_edge_alpha<<<GB_EDGE, 256>>>(srce, dste, ea, 1);
    k_softmax<<<GB_WARP, 256>>>();
    k_agg_csr<<<GB_WARP, 256>>>(W2);
    k_epi<8><<<(NN + 31) / 32, 256>>>(b2, l5W, l5b);

    // ---- classifier ----
    k_clf<<<(LL + 255) / 256, 256>>>(eli, ela, cW, cb, out);
}

// round 7
// speedup vs baseline: 1.2508x; 1.2508x over previous
#include <cuda_runtime.h>
#include <cuda_fp16.h>
#include <math.h>

#define NN  50000   // nodes
#define EE  800000  // edges
#define LL  100000  // label edges
#define HH  8       // heads
#define FD  32      // hidden
#define HC  256     // H*C

// ---------------- scratch (device globals) --------------------------------------
__device__ float  g_x[NN * FD];
__device__ __half g_hh[(size_t)NN * HC];
__device__ float  g_alsrc[NN * HH];
__device__ float  g_aldst[NN * HH];
__device__ float  g_alpha[(size_t)EE * HH]; // ex = exp(lrelu(alpha)), CSR order
__device__ float  g_agg[(size_t)NN * HC];
__device__ float  g_x5[NN * HH];
__device__ float  g_Psrc[2][FD * HH];
__device__ float  g_Pdst[2][FD * HH];
__device__ float  g_M[2][HH * HH];
// CSR by destination
__device__ int g_deg[NN];
__device__ int g_rowptr[NN + 1];
__device__ int g_cursor[NN];
__device__ int g_srcp[EE];   // src node per CSR slot
__device__ int g_slot[EE];   // CSR slot per original edge

// ---------------- precompute both layers: P_src/P_dst [32,8], M [8,8] ----------
__global__ void k_precompute(const float* __restrict__ W1,  const float* __restrict__ as1,
                             const float* __restrict__ ad1, const float* __restrict__ We1,
                             const float* __restrict__ ae1,
                             const float* __restrict__ W2,  const float* __restrict__ as2,
                             const float* __restrict__ ad2, const float* __restrict__ We2,
                             const float* __restrict__ ae2)
{
    int layer = blockIdx.x;
    const float* W   = layer ? W2  : W1;
    const float* a_s = layer ? as2 : as1;
    const float* a_d = layer ? ad2 : ad1;
    const float* We  = layer ? We2 : We1;
    const float* a_e = layer ? ae2 : ae1;

    int t = threadIdx.x;           // 256 threads
    int f = t >> 3, h = t & 7;
    float ss = 0.f, sd = 0.f;
    #pragma unroll 8
    for (int c = 0; c < FD; c++) {
        float w = W[f * HC + h * FD + c];
        ss = fmaf(w, a_s[h * FD + c], ss);
        sd = fmaf(w, a_d[h * FD + c], sd);
    }
    g_Psrc[layer][f * HH + h] = ss;
    g_Pdst[layer][f * HH + h] = sd;
    if (t < 64) {
        int k = t >> 3;
        float sm = 0.f;
        #pragma unroll 8
        for (int c = 0; c < FD; c++)
            sm = fmaf(We[k * HC + h * FD + c], a_e[h * FD + c], sm);
        g_M[layer][k * HH + h] = sm;
    }
}

// ---------------- CSR build -----------------------------------------------------
__global__ void k_zero_deg(void) {
    int i = blockIdx.x * 256 + threadIdx.x;
    if (i < NN) g_deg[i] = 0;
}
__global__ void k_hist(const int* __restrict__ dst) {
    int e = blockIdx.x * 256 + threadIdx.x;
    if (e < EE) atomicAdd(&g_deg[dst[e]], 1);
}
__global__ void __launch_bounds__(1024)
k_scan(void) {
    const int CH = (NN + 1023) / 1024;   // 49
    __shared__ int sums[1024];
    int t = threadIdx.x;
    int base = t * CH;
    int s = 0;
    for (int i = 0; i < CH; i++) {
        int idx = base + i;
        if (idx < NN) s += g_deg[idx];
    }
    sums[t] = s;
    __syncthreads();
    for (int off = 1; off < 1024; off <<= 1) {
        int v = (t >= off) ? sums[t - off] : 0;
        __syncthreads();
        sums[t] += v;
        __syncthreads();
    }
    int run = (t > 0) ? sums[t - 1] : 0;
    for (int i = 0; i < CH; i++) {
        int idx = base + i;
        if (idx < NN) {
            g_rowptr[idx] = run;
            g_cursor[idx] = run;
            run += g_deg[idx];
        }
    }
    if (t == 1023) g_rowptr[NN] = run;
}
__global__ void k_scatter(const int* __restrict__ src, const int* __restrict__ dst) {
    int e = blockIdx.x * 256 + threadIdx.x;
    if (e >= EE) return;
    int d = dst[e];
    int slot = atomicAdd(&g_cursor[d], 1);
    g_srcp[slot] = src[e];   // scattered store
    g_slot[e]    = slot;     // coalesced store
}

// ---------------- node transform: h = x@W (fp16), al_src/al_dst ----------------
__global__ void __launch_bounds__(256)
k_node(const float* __restrict__ xin, const int* __restrict__ ids,
       const float* __restrict__ W, int layer)
{
    __shared__ float Ws[FD * HC];      // 32KB
    __shared__ float xs[32 * 36];
    __shared__ float Ps[FD * HH], Pd[FD * HH];
    int t  = threadIdx.x;
    int n0 = blockIdx.x * 32;

    for (int i = t; i < FD * HC; i += 256) Ws[i] = W[i];
    Ps[t] = g_Psrc[layer][t];
    Pd[t] = g_Pdst[layer][t];
    const float* xp = xin ? xin : g_x;
    for (int i = t; i < 32 * FD; i += 256) {
        int n = i >> 5, k = i & 31;
        int node = n0 + n;
        float v = 0.f;
        if (node < NN) {
            int r = ids ? ids[node] : node;
            v = xp[(size_t)r * FD + k];
        }
        xs[n * 36 + k] = v;
    }
    __syncthreads();

    float acc[32];
    #pragma unroll
    for (int n = 0; n < 32; n++) acc[n] = 0.f;
    #pragma unroll
    for (int kk = 0; kk < 8; kk++) {
        float w0 = Ws[(kk * 4 + 0) * HC + t];
        float w1 = Ws[(kk * 4 + 1) * HC + t];
        float w2 = Ws[(kk * 4 + 2) * HC + t];
        float w3 = Ws[(kk * 4 + 3) * HC + t];
        #pragma unroll
        for (int n = 0; n < 32; n++) {
            float4 xv = *(const float4*)&xs[n * 36 + kk * 4];
            acc[n] = fmaf(xv.x, w0, acc[n]);
            acc[n] = fmaf(xv.y, w1, acc[n]);
            acc[n] = fmaf(xv.z, w2, acc[n]);
            acc[n] = fmaf(xv.w, w3, acc[n]);
        }
    }
    #pragma unroll
    for (int n = 0; n < 32; n++)
        if (n0 + n < NN) g_hh[(size_t)(n0 + n) * HC + t] = __float2half(acc[n]);

    {
        int n = t >> 3, h = t & 7;
        if (n0 + n < NN) {
            float ss = 0.f, sd = 0.f;
            #pragma unroll
            for (int k = 0; k < FD; k++) {
                float xv = xs[n * 36 + k];
                ss = fmaf(xv, Ps[k * HH + h], ss);
                sd = fmaf(xv, Pd[k * HH + h], sd);
            }
            g_alsrc[(n0 + n) * HH + h] = ss;
            g_aldst[(n0 + n) * HH + h] = sd;
        }
    }
}

// ---- edge: ex = exp(lrelu(al_src[s]+al_dst[d]+ea@M)) -> CSR slot (no max) -----
__global__ void __launch_bounds__(256)
k_edge_alpha(const int* __restrict__ src, const int* __restrict__ dst,
             const float* __restrict__ ea, int layer)
{
    __shared__ float Ms[64];
    if (threadIdx.x < 64) Ms[threadIdx.x] = g_M[layer][threadIdx.x];
    __syncthreads();
    int e = blockIdx.x * 256 + threadIdx.x;
    if (e >= EE) return;
    int s = src[e], d = dst[e];
    int p = g_slot[e];

    float4 e0 = *(const float4*)(ea + (size_t)e * 8);
    float4 e1 = *(const float4*)(ea + (size_t)e * 8 + 4);
    float4 s0 = *(const float4*)(g_alsrc + (size_t)s * 8);
    float4 s1 = *(const float4*)(g_alsrc + (size_t)s * 8 + 4);
    float4 d0 = *(const float4*)(g_aldst + (size_t)d * 8);
    float4 d1 = *(const float4*)(g_aldst + (size_t)d * 8 + 4);

    float al[8] = { s0.x + d0.x, s0.y + d0.y, s0.z + d0.z, s0.w + d0.w,
                    s1.x + d1.x, s1.y + d1.y, s1.z + d1.z, s1.w + d1.w };
    float ev[8] = { e0.x, e0.y, e0.z, e0.w, e1.x, e1.y, e1.z, e1.w };
    #pragma unroll
    for (int k = 0; k < 8; k++)
        #pragma unroll
        for (int h = 0; h < 8; h++)
            al[h] = fmaf(ev[k], Ms[k * 8 + h], al[h]);
    #pragma unroll
    for (int h = 0; h < 8; h++) {
        float a = al[h] > 0.f ? al[h] : 0.2f * al[h];
        al[h] = __expf(a);                 // softmax is shift-invariant; |a| is O(1)
    }

    *(float4*)(g_alpha + (size_t)p * 8)     = make_float4(al[0], al[1], al[2], al[3]);
    *(float4*)(g_alpha + (size_t)p * 8 + 4) = make_float4(al[4], al[5], al[6], al[7]);
}

// ---- heavy: agg[n] = (sum h[src]*ex) / (sum ex)  (warp/node, 8-edge MLP, -------
//      denominator accumulated inline from the already-loaded weights) ----------
__global__ void __launch_bounds__(256)
k_agg_csr(void)
{
    int n    = (blockIdx.x * 256 + threadIdx.x) >> 5;
    int lane = threadIdx.x & 31;
    if (n >= NN) return;
    int r0 = g_rowptr[n], r1 = g_rowptr[n + 1];

    int head = lane >> 2;      // head owning cols lane*8 .. lane*8+7
    int eg   = lane >> 3;      // weight-slot edge subgroup 0..3
    float acc0 = 0.f, acc1 = 0.f, acc2 = 0.f, acc3 = 0.f;
    float acc4 = 0.f, acc5 = 0.f, acc6 = 0.f, acc7 = 0.f;
    float dsum = 0.f;          // partial denom for head = lane&7

    for (int p = r0; p < r1; p += 8) {
        int cnt = r1 - p;
        // 8 edges' ex weights = 64 consecutive floats; two coalesced lane loads
        size_t wbase = (size_t)p * 8;
        size_t wlim  = (size_t)r1 * 8 - 1;
        size_t ia = wbase + lane;      if (ia > wlim) ia = wlim;
        size_t ib = wbase + 32 + lane; if (ib > wlim) ib = wlim;
        float w_a = g_alpha[ia];
        float w_b = g_alpha[ib];
        // denom: only count valid slots (clamped dup reads excluded)
        if (eg < cnt)     dsum += w_a;
        if (eg + 4 < cnt) dsum += w_b;

        int sj[8];
        #pragma unroll
        for (int j = 0; j < 8; j++) {
            int pp = p + j; if (pp >= r1) pp = r1 - 1;
            sj[j] = g_srcp[pp];
        }
        // issue all gathers back-to-back (MLP=8 per lane)
        uint4 v[8];
        #pragma unroll
        for (int j = 0; j < 8; j++)
            v[j] = *(const uint4*)(g_hh + (size_t)sj[j] * HC + lane * 8);
        #pragma unroll
        for (int j = 0; j < 8; j++) {
            float w = __shfl_sync(0xffffffffu, (j < 4) ? w_a : w_b,
                                  (j & 3) * 8 + head);
            if (j >= cnt) w = 0.f;
            float2 f0 = __half22float2(*(const __half2*)&v[j].x);
            float2 f1 = __half22float2(*(const __half2*)&v[j].y);
            float2 f2 = __half22float2(*(const __half2*)&v[j].z);
            float2 f3 = __half22float2(*(const __half2*)&v[j].w);
            acc0 = fmaf(f0.x, w, acc0); acc1 = fmaf(f0.y, w, acc1);
            acc2 = fmaf(f1.x, w, acc2); acc3 = fmaf(f1.y, w, acc3);
            acc4 = fmaf(f2.x, w, acc4); acc5 = fmaf(f2.y, w, acc5);
            acc6 = fmaf(f3.x, w, acc6); acc7 = fmaf(f3.y, w, acc7);
        }
    }
    // reduce denom across the 4 edge subgroups (lanes sharing lane&7)
    dsum += __shfl_xor_sync(0xffffffffu, dsum, 8);
    dsum += __shfl_xor_sync(0xffffffffu, dsum, 16);
    // fetch this lane's column-head denom from lane==head (lanes 0..7 hold heads 0..7)
    float den  = __shfl_sync(0xffffffffu, dsum, head);
    float rinv = 1.f / (den + 1e-16f);

    float* po = g_agg + (size_t)n * HC + lane * 8;
    *(float4*)(po)     = make_float4(acc0 * rinv, acc1 * rinv, acc2 * rinv, acc3 * rinv);
    *(float4*)(po + 4) = make_float4(acc4 * rinv, acc5 * rinv, acc6 * rinv, acc7 * rinv);
}

// ---------------- epilogue: y = relu(agg + b) @ LW + lb ------------------------
template <int NJ>
__global__ void __launch_bounds__(256)
k_epi(const float* __restrict__ bias, const float* __restrict__ LW,
      const float* __restrict__ lb)
{
    constexpr int NODES = 256 / NJ;
    __shared__ float rows[NODES * 260];
    __shared__ float LWt[NJ * 260];       // transposed, padded stride
    int t  = threadIdx.x;
    int n0 = blockIdx.x * NODES;

    for (int i = t; i < HC * NJ; i += 256) {
        int c = i / NJ, j = i % NJ;
        LWt[j * 260 + c] = LW[i];
    }
    for (int i = t; i < NODES * HC; i += 256) {
        int n = i >> 8, c = i & 255;
        float v = 0.f;
        if (n0 + n < NN) v = g_agg[(size_t)(n0 + n) * HC + c] + bias[c];
        rows[n * 260 + c] = fmaxf(v, 0.f);
    }
    __syncthreads();

    int n = t / NJ, j = t % NJ;
    if (n0 + n < NN) {
        float acc = lb[j];
        #pragma unroll
        for (int c4 = 0; c4 < 64; c4++) {
            float4 r  = *(const float4*)&rows[n * 260 + c4 * 4];
            float4 wv = *(const float4*)&LWt[j * 260 + c4 * 4];
            acc = fmaf(r.x, wv.x, acc);
            acc = fmaf(r.y, wv.y, acc);
            acc = fmaf(r.z, wv.z, acc);
            acc = fmaf(r.w, wv.w, acc);
        }
        if (NJ == 32) g_x [(size_t)(n0 + n) * 32 + j] = acc;
        else          g_x5[(size_t)(n0 + n) * 8  + j] = acc;
    }
}

// ---------------- classifier over label edges ---------------------------------
__global__ void __launch_bounds__(256)
k_clf(const int* __restrict__ eli, const float* __restrict__ ela,
      const float* __restrict__ cW, const float* __restrict__ cb,
      float* __restrict__ outp)
{
    __shared__ float Ws[128], Bs[8];
    if (threadIdx.x < 128) Ws[threadIdx.x] = cW[threadIdx.x];
    if (threadIdx.x < 8)   Bs[threadIdx.x] = cb[threadIdx.x];
    __syncthreads();
    int l = blockIdx.x * 256 + threadIdx.x;
    if (l >= LL) return;
    int u = eli[l], m = eli[LL + l];

    float4 u0 = *(const float4*)(g_x5 + (size_t)u * 8);
    float4 u1 = *(const float4*)(g_x5 + (size_t)u * 8 + 4);
    float4 m0 = *(const float4*)(g_x5 + (size_t)m * 8);
    float4 m1 = *(const float4*)(g_x5 + (size_t)m * 8 + 4);
    float4 a0 = *(const float4*)(ela + (size_t)l * 8);
    float4 a1 = *(const float4*)(ela + (size_t)l * 8 + 4);
    float xu[8] = { u0.x, u0.y, u0.z, u0.w, u1.x, u1.y, u1.z, u1.w };
    float xm[8] = { m0.x, m0.y, m0.z, m0.w, m1.x, m1.y, m1.z, m1.w };
    float ev[8] = { a0.x, a0.y, a0.z, a0.w, a1.x, a1.y, a1.z, a1.w };

    float dot = 0.f;
    #pragma unroll
    for (int j = 0; j < 8; j++) {
        float fu = Bs[j];
        #pragma unroll
        for (int k = 0; k < 8; k++) fu = fmaf(xu[k], Ws[k * 8 + j], fu);
        #pragma unroll
        for (int k = 0; k < 8; k++) fu = fmaf(ev[k], Ws[(8 + k) * 8 + j], fu);
        dot = fmaf(fu, xm[j], dot);
    }
    outp[l] = 1.f / (1.f + expf(-dot));
}

// ---------------- launch -------------------------------------------------------
extern "C" void kernel_launch(void* const* d_in, const int* in_sizes, int n_in,
                              void* d_out, int out_size)
{
    const int*   node_ids = (const int*)d_in[0];
    const int*   ei   = (const int*)d_in[1];
    const int*   eli  = (const int*)d_in[2];
    const float* ea   = (const float*)d_in[4];
    const float* ela  = (const float*)d_in[5];
    const float* emb  = (const float*)d_in[6];
    const float* W1   = (const float*)d_in[7];
    const float* as1  = (const float*)d_in[8];
    const float* ad1  = (const float*)d_in[9];
    const float* We1  = (const float*)d_in[10];
    const float* ae1  = (const float*)d_in[11];
    const float* b1   = (const float*)d_in[12];
    const float* l1W  = (const float*)d_in[13];
    const float* l1b  = (const float*)d_in[14];
    const float* W2   = (const float*)d_in[15];
    const float* as2  = (const float*)d_in[16];
    const float* ad2  = (const float*)d_in[17];
    const float* We2  = (const float*)d_in[18];
    const float* ae2  = (const float*)d_in[19];
    const float* b2   = (const float*)d_in[20];
    const float* l5W  = (const float*)d_in[21];
    const float* l5b  = (const float*)d_in[22];
    const float* cW   = (const float*)d_in[23];
    const float* cb   = (const float*)d_in[24];
    float* out = (float*)d_out;

    const int* srce = ei;
    const int* dste = ei + EE;

    const int GB_NODE = (NN + 31) / 32;            // 1563
    const int GB_EDGE = (EE + 255) / 256;          // 3125
    const int GB_WARP = (NN * 32 + 255) / 256;     // 6250 (warp per node)
    const int GB_N256 = (NN + 255) / 256;          // 196

    // CSR build (shared by both layers)
    k_zero_deg<<<GB_N256, 256>>>();
    k_hist<<<GB_EDGE, 256>>>(dste);
    k_scan<<<1, 1024>>>();
    k_scatter<<<GB_EDGE, 256>>>(srce, dste);

    k_precompute<<<2, 256>>>(W1, as1, ad1, We1, ae1, W2, as2, ad2, We2, ae2);

    // ---- layer 1 ----
    k_node<<<GB_NODE, 256>>>(emb, node_ids, W1, 0);
    k_edge_alpha<<<GB_EDGE, 256>>>(srce, dste, ea, 0);
    k_agg_csr<<<GB_WARP, 256>>>();
    k_epi<32><<<(NN + 7) / 8, 256>>>(b1, l1W, l1b);

    // ---- layer 2 ----
    k_node<<<GB_NODE, 256>>>(nullptr, nullptr, W2, 1);
    k_edge_alpha<<<GB_EDGE, 256>>>(srce, dste, ea, 1);
    k_agg_csr<<<GB_WARP, 256>>>();
    k_epi<8><<<(NN + 31) / 32, 256>>>(b2, l5W, l5b);

    // ---- classifier ----
    k_clf<<<(LL + 255) / 256, 256>>>(eli, ela, cW, cb, out);
}